// round 13
// baseline (speedup 1.0000x reference)
#include <cuda_runtime.h>
#include <cuda_bf16.h>

#define NUM_SEQS   32
#define KV_LEN     2048
#define NUM_HEADS  16
#define HEAD_SIZE  128
#define SCALE      0.08838834764831845f

#define THREADS    256
#define WARPS      (THREADS / 32)   // 8
#define ROWS_PER_GRP 4              // rows prefetched per warp per iter

// one block per (seq, head): streams K/V rows for that head, online softmax.
// reshape_and_cache scatter is fused away: the row whose slot equals
// slot_mapping[s] reads the fresh k/v inputs instead of the stale cache row.
//
// CONVERGED FINAL FORM. Eight runs of this exact source: 150.0-152.3 us
// (mean 151.6, sigma ~0.65). DRAM 88-90%, HBM ~7.1 TB/s = 87-89% of spec —
// the B300 channel-uniformity ceiling (88-92% for all strides per
// B300_MICROARCH). Analytical floor 1.07 GB / (0.89 * 8 TB/s) ~= 150.3 us
// -> >99% of achievable. Falsified: __ldcs (+2.5us), SW-pipelined 2x MLP
// @ half occupancy (+3us). Rejected on model/HW constants: split-KV (one
// co-resident wave, no tail), TMA (LTS path-independent; HBM-bound),
// address restructuring (HBM hash not pattern-addressable), 512-thr blocks
// (RF cliff -> 16 warps/SM), ROWS_PER_GRP 2/8 (MLP loss / reg cliff),
// lane-transposed dot product (compute pipes are 15% busy, not binding).
__global__ __launch_bounds__(THREADS, 1)
void attn_decode_kernel(const float* __restrict__ q,
                        const float* __restrict__ knew,
                        const float* __restrict__ vnew,
                        const float* __restrict__ kv_cache,
                        const void* __restrict__ slot_mapping,
                        int slot_is_i64,
                        float* __restrict__ out)
{
    const int sh   = blockIdx.x;          // s * NUM_HEADS + h
    const int s    = sh >> 4;
    const int h    = sh & (NUM_HEADS - 1);
    const int tid  = threadIdx.x;
    const int w    = tid >> 5;
    const int lane = tid & 31;

    const long long row_stride = (long long)NUM_HEADS * HEAD_SIZE;          // 2048 floats
    const long long plane      = (long long)NUM_SEQS * KV_LEN * row_stride; // K->V offset
    const float* Kbase = kv_cache + (long long)s * KV_LEN * row_stride + (long long)h * HEAD_SIZE;
    const float* Vbase = Kbase + plane;

    long long slot;
    if (slot_is_i64) slot = ((const long long*)slot_mapping)[s];
    else             slot = (long long)((const int*)slot_mapping)[s];
    const int new_pos = (int)(slot - (long long)s * KV_LEN);

    // q fragment: lane owns dims [lane*4, lane*4+4)
    float4 q4 = ((const float4*)(q + (long long)sh * HEAD_SIZE))[lane];
    q4.x *= SCALE; q4.y *= SCALE; q4.z *= SCALE; q4.w *= SCALE;

    const float4 kin4 = ((const float4*)(knew + (long long)sh * HEAD_SIZE))[lane];
    const float4 vin4 = ((const float4*)(vnew + (long long)sh * HEAD_SIZE))[lane];

    float  m   = -1e30f;
    float  l   = 0.0f;
    float4 acc = make_float4(0.f, 0.f, 0.f, 0.f);

    // warp w handles rows t = w*4 + i (+32 per iter); 256 rows per warp total
    for (int t0 = w * ROWS_PER_GRP; t0 < KV_LEN; t0 += WARPS * ROWS_PER_GRP) {
        float4 kr[ROWS_PER_GRP], vr[ROWS_PER_GRP];
        #pragma unroll
        for (int i = 0; i < ROWS_PER_GRP; ++i) {
            const long long t = t0 + i;
            kr[i] = ((const float4*)(Kbase + t * row_stride))[lane];
            vr[i] = ((const float4*)(Vbase + t * row_stride))[lane];
        }
        #pragma unroll
        for (int i = 0; i < ROWS_PER_GRP; ++i) {
            const int t = t0 + i;
            if (t == new_pos) { kr[i] = kin4; vr[i] = vin4; }  // fused scatter

            float sc = kr[i].x * q4.x + kr[i].y * q4.y + kr[i].z * q4.z + kr[i].w * q4.w;
            #pragma unroll
            for (int off = 16; off > 0; off >>= 1)
                sc += __shfl_xor_sync(0xffffffffu, sc, off);

            const float m_new = fmaxf(m, sc);
            const float corr  = __expf(m - m_new);
            const float p     = __expf(sc - m_new);
            l     = l * corr + p;
            acc.x = acc.x * corr + p * vr[i].x;
            acc.y = acc.y * corr + p * vr[i].y;
            acc.z = acc.z * corr + p * vr[i].z;
            acc.w = acc.w * corr + p * vr[i].w;
            m     = m_new;
        }
    }

    // cross-warp merge
    __shared__ float4 acc_s[WARPS][32];
    __shared__ float  m_s[WARPS];
    __shared__ float  l_s[WARPS];

    acc_s[w][lane] = acc;
    if (lane == 0) { m_s[w] = m; l_s[w] = l; }
    __syncthreads();

    if (tid < HEAD_SIZE) {
        float M = m_s[0];
        #pragma unroll
        for (int ww = 1; ww < WARPS; ++ww) M = fmaxf(M, m_s[ww]);
        float num = 0.f, den = 0.f;
        const float* accf = (const float*)acc_s;   // [WARPS][128]
        #pragma unroll
        for (int ww = 0; ww < WARPS; ++ww) {
            const float sc = __expf(m_s[ww] - M);
            num += sc * accf[ww * HEAD_SIZE + tid];
            den += sc * l_s[ww];
        }
        out[(long long)sh * HEAD_SIZE + tid] = num / den;
    }
}

extern "C" void kernel_launch(void* const* d_in, const int* in_sizes, int n_in,
                              void* d_out, int out_size)
{
    const float* q   = (const float*)d_in[0];
    const float* k   = (const float*)d_in[1];
    const float* v   = (const float*)d_in[2];
    const float* kvc = (const float*)d_in[3];
    const void*  sm  = d_in[4];
    float* out = (float*)d_out;

    // If the harness exposed slot_mapping as int64, the 32-bit element count
    // doubles (64 words for 32 seqs). Branch on that.
    const int slot_is_i64 = (in_sizes[4] >= 2 * NUM_SEQS) ? 1 : 0;

    attn_decode_kernel<<<NUM_SEQS * NUM_HEADS, THREADS>>>(q, k, v, kvc, sm, slot_is_i64, out);
}

// round 14
// speedup vs baseline: 1.0147x; 1.0147x over previous
#include <cuda_runtime.h>
#include <cuda_bf16.h>

#define NUM_SEQS   32
#define KV_LEN     2048
#define NUM_HEADS  16
#define HEAD_SIZE  128
#define SCALE      0.08838834764831845f

#define THREADS    256
#define WARPS      (THREADS / 32)   // 8
#define ROWS_PER_GRP 4              // rows prefetched per warp per iter

// one block per (seq, head): streams K/V rows for that head, online softmax.
// reshape_and_cache scatter is fused away: the row whose slot equals
// slot_mapping[s] reads the fresh k/v inputs instead of the stale cache row.
//
// CONVERGED FINAL FORM. Nine runs of this exact source: 150.0-152.3 us
// (mean 151.7, sigma ~0.6). DRAM 88-90%, HBM ~7.1 TB/s = 87-89% of spec —
// the B300 channel-uniformity ceiling (88-92% for all strides per
// B300_MICROARCH). Analytical floor 1.07 GB / (0.89 * 8 TB/s) ~= 150.3 us
// -> ~99% of achievable. Falsified: __ldcs (+2.5us), SW-pipelined 2x MLP
// @ half occupancy (+3us). Rejected on model/HW constants: split-KV (one
// co-resident wave, no tail), TMA (LTS path-independent; HBM-bound),
// address restructuring (HBM hash not pattern-addressable), 512-thr blocks
// (RF cliff -> 16 warps/SM), ROWS_PER_GRP 2/8 (MLP loss / reg cliff),
// lane-transposed dot product (compute pipes 15% busy, not binding).
__global__ __launch_bounds__(THREADS, 1)
void attn_decode_kernel(const float* __restrict__ q,
                        const float* __restrict__ knew,
                        const float* __restrict__ vnew,
                        const float* __restrict__ kv_cache,
                        const void* __restrict__ slot_mapping,
                        int slot_is_i64,
                        float* __restrict__ out)
{
    const int sh   = blockIdx.x;          // s * NUM_HEADS + h
    const int s    = sh >> 4;
    const int h    = sh & (NUM_HEADS - 1);
    const int tid  = threadIdx.x;
    const int w    = tid >> 5;
    const int lane = tid & 31;

    const long long row_stride = (long long)NUM_HEADS * HEAD_SIZE;          // 2048 floats
    const long long plane      = (long long)NUM_SEQS * KV_LEN * row_stride; // K->V offset
    const float* Kbase = kv_cache + (long long)s * KV_LEN * row_stride + (long long)h * HEAD_SIZE;
    const float* Vbase = Kbase + plane;

    long long slot;
    if (slot_is_i64) slot = ((const long long*)slot_mapping)[s];
    else             slot = (long long)((const int*)slot_mapping)[s];
    const int new_pos = (int)(slot - (long long)s * KV_LEN);

    // q fragment: lane owns dims [lane*4, lane*4+4)
    float4 q4 = ((const float4*)(q + (long long)sh * HEAD_SIZE))[lane];
    q4.x *= SCALE; q4.y *= SCALE; q4.z *= SCALE; q4.w *= SCALE;

    const float4 kin4 = ((const float4*)(knew + (long long)sh * HEAD_SIZE))[lane];
    const float4 vin4 = ((const float4*)(vnew + (long long)sh * HEAD_SIZE))[lane];

    float  m   = -1e30f;
    float  l   = 0.0f;
    float4 acc = make_float4(0.f, 0.f, 0.f, 0.f);

    // warp w handles rows t = w*4 + i (+32 per iter); 256 rows per warp total
    for (int t0 = w * ROWS_PER_GRP; t0 < KV_LEN; t0 += WARPS * ROWS_PER_GRP) {
        float4 kr[ROWS_PER_GRP], vr[ROWS_PER_GRP];
        #pragma unroll
        for (int i = 0; i < ROWS_PER_GRP; ++i) {
            const long long t = t0 + i;
            kr[i] = ((const float4*)(Kbase + t * row_stride))[lane];
            vr[i] = ((const float4*)(Vbase + t * row_stride))[lane];
        }
        #pragma unroll
        for (int i = 0; i < ROWS_PER_GRP; ++i) {
            const int t = t0 + i;
            if (t == new_pos) { kr[i] = kin4; vr[i] = vin4; }  // fused scatter

            float sc = kr[i].x * q4.x + kr[i].y * q4.y + kr[i].z * q4.z + kr[i].w * q4.w;
            #pragma unroll
            for (int off = 16; off > 0; off >>= 1)
                sc += __shfl_xor_sync(0xffffffffu, sc, off);

            const float m_new = fmaxf(m, sc);
            const float corr  = __expf(m - m_new);
            const float p     = __expf(sc - m_new);
            l     = l * corr + p;
            acc.x = acc.x * corr + p * vr[i].x;
            acc.y = acc.y * corr + p * vr[i].y;
            acc.z = acc.z * corr + p * vr[i].z;
            acc.w = acc.w * corr + p * vr[i].w;
            m     = m_new;
        }
    }

    // cross-warp merge
    __shared__ float4 acc_s[WARPS][32];
    __shared__ float  m_s[WARPS];
    __shared__ float  l_s[WARPS];

    acc_s[w][lane] = acc;
    if (lane == 0) { m_s[w] = m; l_s[w] = l; }
    __syncthreads();

    if (tid < HEAD_SIZE) {
        float M = m_s[0];
        #pragma unroll
        for (int ww = 1; ww < WARPS; ++ww) M = fmaxf(M, m_s[ww]);
        float num = 0.f, den = 0.f;
        const float* accf = (const float*)acc_s;   // [WARPS][128]
        #pragma unroll
        for (int ww = 0; ww < WARPS; ++ww) {
            const float sc = __expf(m_s[ww] - M);
            num += sc * accf[ww * HEAD_SIZE + tid];
            den += sc * l_s[ww];
        }
        out[(long long)sh * HEAD_SIZE + tid] = num / den;
    }
}

extern "C" void kernel_launch(void* const* d_in, const int* in_sizes, int n_in,
                              void* d_out, int out_size)
{
    const float* q   = (const float*)d_in[0];
    const float* k   = (const float*)d_in[1];
    const float* v   = (const float*)d_in[2];
    const float* kvc = (const float*)d_in[3];
    const void*  sm  = d_in[4];
    float* out = (float*)d_out;

    // If the harness exposed slot_mapping as int64, the 32-bit element count
    // doubles (64 words for 32 seqs). Branch on that.
    const int slot_is_i64 = (in_sizes[4] >= 2 * NUM_SEQS) ? 1 : 0;

    attn_decode_kernel<<<NUM_SEQS * NUM_HEADS, THREADS>>>(q, k, v, kvc, sm, slot_is_i64, out);
}